// round 13
// baseline (speedup 1.0000x reference)
#include <cuda_runtime.h>
#include <cstdint>

// B=256, T=64 (K), S=16, U=4 -> P=256 pixels, O=1024 outputs/pixel.
//
// Model (calibrated R9-R12): fma floor 227k cyc (FFMA2 128 MAC/cyc/SM); LDS
// charged per-lane (no broadcast dedup); duration = floor / fma-duty.
// R13: A (the 4-way-duplicated operand) moves from LDS to __ldg -- the L1TEX
// coalescer dedups duplicate addresses, cutting L1 data-path demand ~38% and
// breaking the fma/crossbar 100/100 deadlock. A stays L1D-resident (both
// co-resident CTAs share the same pixel slice; smem is now only 26 KB).
//
// kernel 1: transpose x -> g_xT32[p][t][b]
// kernel 2: CTA = (bn 16, p 256): C[256 b x 64 o] = A @ W^T + bias.
//           A: __ldg from g_xT32 (b-pairs = natural f32x2).  B: smem, 48B-group
//           layout, 2 LDS.128 + dup movs.  Tile 8b x 8o, acc2[4][8] f32x2.

__device__ float g_xT32[256 * 64 * 256];  // [p][t][b], 16 MB

__device__ __forceinline__ uint32_t smem_u32(const void* p) {
    uint32_t a;
    asm("{ .reg .u64 t; cvta.to.shared.u64 t, %1; cvt.u32.u64 %0, t; }" : "=r"(a) : "l"(p));
    return a;
}
__device__ __forceinline__ void cp16(uint32_t sdst, const void* g) {
    asm volatile("cp.async.cg.shared.global [%0], [%1], 16;" :: "r"(sdst), "l"(g));
}
__device__ __forceinline__ unsigned long long dupf2(float v) {
    unsigned long long r;
    asm("mov.b64 %0, {%1, %1};" : "=l"(r) : "f"(v));
    return r;
}
__device__ __forceinline__ float2 unpackf2(unsigned long long v) {
    float2 r;
    asm("mov.b64 {%0, %1}, %2;" : "=f"(r.x), "=f"(r.y) : "l"(v));
    return r;
}

// ---------------------------------------------------------------------------
// Transpose: x[b][t][p] -> g_xT32[p*16384 + t*256 + b]
// ---------------------------------------------------------------------------
__global__ void transpose32_kernel(const float* __restrict__ x) {
    __shared__ float tile[32][33];
    int p0 = blockIdx.x * 32, b0 = blockIdx.y * 32, t = blockIdx.z;
    int tx = threadIdx.x, ty = threadIdx.y;
#pragma unroll
    for (int k = 0; k < 4; k++) {
        int br = ty + k * 8;
        tile[br][tx] = x[(size_t)(b0 + br) * 16384 + (size_t)t * 256 + p0 + tx];
    }
    __syncthreads();
#pragma unroll
    for (int k = 0; k < 4; k++) {
        int pr = ty + k * 8;
        g_xT32[(size_t)(p0 + pr) * 16384 + (size_t)t * 256 + b0 + tx] = tile[tx][pr];
    }
}

// ---------------------------------------------------------------------------
// GEMM: C[256 b x 64 o] per CTA. 256 threads = 32 tb (8 b) x 8 to (8 o).
// Wp layout: value (k, o) at float k*WROW + (o>>3)*12 + (o&7)  [48B groups]
// ---------------------------------------------------------------------------
#define WROW 100
#define WP_F (64 * WROW)             // 25.6 KB
#define SMEM_BYTES ((WP_F + 64) * 4)

__global__ __launch_bounds__(256, 2) void gemm_kernel(const float* __restrict__ Wg_all,
                                                      const float* __restrict__ bias,
                                                      float* __restrict__ out) {
    extern __shared__ float smem[];
    float* Wp = smem;                   // [64 k][WROW]
    float* bias_s = smem + WP_F;        // [64]

    const int bn = blockIdx.x;   // 0..15 (o tile of 64)
    const int p  = blockIdx.y;
    const int tid = threadIdx.x;
    const int tb = tid >> 3;     // 0..31: b rows tb*8 .. tb*8+7
    const int to = tid & 7;      // 0..7:  o = bn*64 + to*8 + j

    if (tid < 16) cp16(smem_u32(bias_s) + tid * 16, bias + (size_t)p * 1024 + bn * 64 + tid * 4);
    asm volatile("cp.async.commit_group;");

    // W: [64 o][64 k] -> Wp[k][(o>>3)*12 + (o&7)]
    const float* Wg = Wg_all + ((size_t)p << 16) + (size_t)(bn * 64) * 64;
#pragma unroll
    for (int i = 0; i < 4; i++) {
        int idx = tid + i * 256;          // 1024 float4s
        int o = idx >> 4;                 // 0..63
        int kc = (idx & 15) << 2;         // 0..60
        float4 v = *(const float4*)(Wg + o * 64 + kc);
        int od = ((o >> 3) * 12) + (o & 7);
        Wp[(kc + 0) * WROW + od] = v.x;
        Wp[(kc + 1) * WROW + od] = v.y;
        Wp[(kc + 2) * WROW + od] = v.z;
        Wp[(kc + 3) * WROW + od] = v.w;
    }
    asm volatile("cp.async.wait_group 0;");
    __syncthreads();

    unsigned long long acc2[4][8];
#pragma unroll
    for (int i = 0; i < 4; i++)
#pragma unroll
        for (int j = 0; j < 8; j++) acc2[i][j] = 0ull;

    // A streamed via __ldg: g_xT32[p][k][tb*8 .. +7], L1-coalesced (4-lane dedup)
    const ulonglong2* Abase = (const ulonglong2*)(g_xT32 + ((size_t)p << 14) + tb * 8);
    const float* Bbase = Wp + to * 12;

#pragma unroll 16
    for (int k = 0; k < 64; k++) {
        ulonglong2 A0 = __ldg(Abase + k * 64);       // 256 floats = 64 ulonglong2 per k-row
        ulonglong2 A1 = __ldg(Abase + k * 64 + 1);
        unsigned long long a2[4] = {A0.x, A0.y, A1.x, A1.y};
        float4 B0 = *(const float4*)(Bbase + k * WROW);
        float4 B1 = *(const float4*)(Bbase + k * WROW + 4);
        unsigned long long bd[8];
        bd[0] = dupf2(B0.x); bd[1] = dupf2(B0.y);
        bd[2] = dupf2(B0.z); bd[3] = dupf2(B0.w);
        bd[4] = dupf2(B1.x); bd[5] = dupf2(B1.y);
        bd[6] = dupf2(B1.z); bd[7] = dupf2(B1.w);
#pragma unroll
        for (int i = 0; i < 4; i++)
#pragma unroll
            for (int j = 0; j < 8; j++) {
                asm("fma.rn.f32x2 %0, %1, %2, %0;"
                    : "+l"(acc2[i][j]) : "l"(a2[i]), "l"(bd[j]));
            }
    }

    // Epilogue: o0 = bn*64 + to*8; j 0..3 -> quad (t,ui), j 4..7 -> (t,ui+1)
    const int i4 = (p >> 4) << 2, j4 = (p & 15) << 2;
    int o0 = bn * 64 + to * 8;
    int t  = o0 >> 4;
    int ui = (o0 >> 2) & 3;               // 0 or 2
    int coloff0 = t * 4096 + (i4 + ui) * 64 + j4;
    int coloff1 = coloff0 + 64;           // ui+1
    float4 bv0 = *(const float4*)&bias_s[to * 8];
    float4 bv1 = *(const float4*)&bias_s[to * 8 + 4];
#pragma unroll
    for (int i = 0; i < 4; i++) {
        float2 c[8];
#pragma unroll
        for (int j = 0; j < 8; j++) c[j] = unpackf2(acc2[i][j]);
        size_t r0 = (size_t)(tb * 8 + 2 * i) * 262144;
        size_t r1 = r0 + 262144;
        *(float4*)(out + r0 + coloff0) =
            make_float4(c[0].x + bv0.x, c[1].x + bv0.y, c[2].x + bv0.z, c[3].x + bv0.w);
        *(float4*)(out + r0 + coloff1) =
            make_float4(c[4].x + bv1.x, c[5].x + bv1.y, c[6].x + bv1.z, c[7].x + bv1.w);
        *(float4*)(out + r1 + coloff0) =
            make_float4(c[0].y + bv0.x, c[1].y + bv0.y, c[2].y + bv0.z, c[3].y + bv0.w);
        *(float4*)(out + r1 + coloff1) =
            make_float4(c[4].y + bv1.x, c[5].y + bv1.y, c[6].y + bv1.z, c[7].y + bv1.w);
    }
}

extern "C" void kernel_launch(void* const* d_in, const int* in_sizes, int n_in,
                              void* d_out, int out_size) {
    const float* x = (const float*)d_in[0];   // (256, 64, 16, 16)
    const float* W = (const float*)d_in[1];   // (256, 1024, 64)
    const float* b = (const float*)d_in[2];   // (256, 1024)
    float* out = (float*)d_out;               // (256, 64, 64, 64)
    (void)in_sizes; (void)n_in; (void)out_size;

    cudaFuncSetAttribute(gemm_kernel, cudaFuncAttributeMaxDynamicSharedMemorySize, SMEM_BYTES);

    transpose32_kernel<<<dim3(8, 8, 64), dim3(32, 8)>>>(x);
    gemm_kernel<<<dim3(16, 256), 256, SMEM_BYTES>>>(W, b, out);
}

// round 15
// speedup vs baseline: 1.3114x; 1.3114x over previous
#include <cuda_runtime.h>
#include <cstdint>

// B=256, T=64 (K), S=16, U=4 -> P=256 pixels, O=1024 outputs/pixel.
//
// Model (R9-R13): fma floor 227k cyc (FFMA2 128 MAC/cyc/SM); LDS per-lane
// charged, no broadcast dedup; LDG loses to LDS at this reuse distance (R13).
// R12 is balanced fma/crossbar 100/100 but runs ~50% duty on dependency
// stalls. R15 = R12 + explicit 1-deep register pipeline (R14 fixed: smem tail
// padded 64 -> 256 floats so the k=63 overshoot prefetch stays in-bounds).
//
// kernel 1: transpose x -> g_xT32[p][t][b]
// kernel 2: CTA = (bn 16, p 256): C[256 b x 64 o] = A @ W^T + bias.
//           As[64 k][256 b] cp.async copy; Wp 48B-group layout (2 LDS.128);
//           tile 8b x 8o, acc2[4][8] f32x2; dup movs on alu pipe.

__device__ float g_xT32[256 * 64 * 256];  // [p][t][b], 16 MB

__device__ __forceinline__ uint32_t smem_u32(const void* p) {
    uint32_t a;
    asm("{ .reg .u64 t; cvta.to.shared.u64 t, %1; cvt.u32.u64 %0, t; }" : "=r"(a) : "l"(p));
    return a;
}
__device__ __forceinline__ void cp16(uint32_t sdst, const void* g) {
    asm volatile("cp.async.cg.shared.global [%0], [%1], 16;" :: "r"(sdst), "l"(g));
}
__device__ __forceinline__ unsigned long long dupf2(float v) {
    unsigned long long r;
    asm("mov.b64 %0, {%1, %1};" : "=l"(r) : "f"(v));
    return r;
}
__device__ __forceinline__ float2 unpackf2(unsigned long long v) {
    float2 r;
    asm("mov.b64 {%0, %1}, %2;" : "=f"(r.x), "=f"(r.y) : "l"(v));
    return r;
}

// ---------------------------------------------------------------------------
// Transpose: x[b][t][p] -> g_xT32[p*16384 + t*256 + b]
// ---------------------------------------------------------------------------
__global__ void transpose32_kernel(const float* __restrict__ x) {
    __shared__ float tile[32][33];
    int p0 = blockIdx.x * 32, b0 = blockIdx.y * 32, t = blockIdx.z;
    int tx = threadIdx.x, ty = threadIdx.y;
#pragma unroll
    for (int k = 0; k < 4; k++) {
        int br = ty + k * 8;
        tile[br][tx] = x[(size_t)(b0 + br) * 16384 + (size_t)t * 256 + p0 + tx];
    }
    __syncthreads();
#pragma unroll
    for (int k = 0; k < 4; k++) {
        int pr = ty + k * 8;
        g_xT32[(size_t)(p0 + pr) * 16384 + (size_t)t * 256 + b0 + tx] = tile[tx][pr];
    }
}

// ---------------------------------------------------------------------------
// GEMM: C[256 b x 64 o] per CTA. 256 threads = 32 tb (8 b) x 8 to (8 o).
// Wp layout: value (k, o) at float k*WROW + (o>>3)*12 + (o&7)  [48B groups]
// ---------------------------------------------------------------------------
#define WROW 100
#define AS_F (64 * 256)              // 64 KB
#define WP_F (64 * WROW)             // 25.6 KB
#define PAD_F 256                    // tail pad: k=63 overshoot prefetch lands here
#define SMEM_BYTES ((AS_F + WP_F + PAD_F) * 4)

__global__ __launch_bounds__(256, 2) void gemm_kernel(const float* __restrict__ Wg_all,
                                                      const float* __restrict__ bias,
                                                      float* __restrict__ out) {
    extern __shared__ float smem[];
    float* As = smem;                   // [64 k][256 b]
    float* Wp = smem + AS_F;            // [64 k][WROW]
    float* bias_s = smem + AS_F + WP_F; // [64] (+192 spare pad)

    const int bn = blockIdx.x;   // 0..15 (o tile of 64)
    const int p  = blockIdx.y;
    const int tid = threadIdx.x;
    const int tb = tid >> 3;     // 0..31: b rows tb*8 .. tb*8+7
    const int to = tid & 7;      // 0..7:  o = bn*64 + to*8 + j

    // A: linear 64 KB copy of g_xT32 p-slice
    const float* Ag = g_xT32 + ((size_t)p << 14);
    uint32_t sA = smem_u32(As);
#pragma unroll
    for (int i = 0; i < 16; i++) {
        int idx = tid + i * 256;         // 4096 chunks of 16B
        cp16(sA + idx * 16, Ag + idx * 4);
    }
    if (tid < 16) cp16(smem_u32(bias_s) + tid * 16, bias + (size_t)p * 1024 + bn * 64 + tid * 4);
    asm volatile("cp.async.commit_group;");

    // W: [64 o][64 k] -> Wp[k][(o>>3)*12 + (o&7)]
    const float* Wg = Wg_all + ((size_t)p << 16) + (size_t)(bn * 64) * 64;
#pragma unroll
    for (int i = 0; i < 4; i++) {
        int idx = tid + i * 256;          // 1024 float4s
        int o = idx >> 4;                 // 0..63
        int kc = (idx & 15) << 2;         // 0..60
        float4 v = *(const float4*)(Wg + o * 64 + kc);
        int od = ((o >> 3) * 12) + (o & 7);
        Wp[(kc + 0) * WROW + od] = v.x;
        Wp[(kc + 1) * WROW + od] = v.y;
        Wp[(kc + 2) * WROW + od] = v.z;
        Wp[(kc + 3) * WROW + od] = v.w;
    }
    asm volatile("cp.async.wait_group 0;");
    __syncthreads();

    unsigned long long acc2[4][8];
#pragma unroll
    for (int i = 0; i < 4; i++)
#pragma unroll
        for (int j = 0; j < 8; j++) acc2[i][j] = 0ull;

    const float* Abase = As + tb * 8;
    const float* Bbase = Wp + to * 12;

    // Explicit 1-deep register pipeline: buf[cur] computed while buf[nxt] loads.
    ulonglong2 Abuf0[2], Abuf1[2];
    float4 Bbuf0[2], Bbuf1[2];
    Abuf0[0] = *(const ulonglong2*)(Abase);
    Abuf1[0] = *(const ulonglong2*)(Abase + 4);
    Bbuf0[0] = *(const float4*)(Bbase);
    Bbuf1[0] = *(const float4*)(Bbase + 4);

#pragma unroll 8
    for (int k = 0; k < 64; k++) {
        int cur = k & 1, nxt = cur ^ 1;
        // Prefetch k+1 (k=63 reads row 64: lands in Wp/pad, in-bounds, unused)
        Abuf0[nxt] = *(const ulonglong2*)(Abase + (k + 1) * 256);
        Abuf1[nxt] = *(const ulonglong2*)(Abase + (k + 1) * 256 + 4);
        Bbuf0[nxt] = *(const float4*)(Bbase + (k + 1) * WROW);
        Bbuf1[nxt] = *(const float4*)(Bbase + (k + 1) * WROW + 4);

        unsigned long long a2[4] = {Abuf0[cur].x, Abuf0[cur].y, Abuf1[cur].x, Abuf1[cur].y};
        unsigned long long bd[8];
        bd[0] = dupf2(Bbuf0[cur].x); bd[1] = dupf2(Bbuf0[cur].y);
        bd[2] = dupf2(Bbuf0[cur].z); bd[3] = dupf2(Bbuf0[cur].w);
        bd[4] = dupf2(Bbuf1[cur].x); bd[5] = dupf2(Bbuf1[cur].y);
        bd[6] = dupf2(Bbuf1[cur].z); bd[7] = dupf2(Bbuf1[cur].w);
#pragma unroll
        for (int i = 0; i < 4; i++)
#pragma unroll
            for (int j = 0; j < 8; j++) {
                asm("fma.rn.f32x2 %0, %1, %2, %0;"
                    : "+l"(acc2[i][j]) : "l"(a2[i]), "l"(bd[j]));
            }
    }

    // Epilogue: o0 = bn*64 + to*8; j 0..3 -> quad (t,ui), j 4..7 -> (t,ui+1)
    const int i4 = (p >> 4) << 2, j4 = (p & 15) << 2;
    int o0 = bn * 64 + to * 8;
    int t  = o0 >> 4;
    int ui = (o0 >> 2) & 3;               // 0 or 2
    int coloff0 = t * 4096 + (i4 + ui) * 64 + j4;
    int coloff1 = coloff0 + 64;           // ui+1
    float4 bv0 = *(const float4*)&bias_s[to * 8];
    float4 bv1 = *(const float4*)&bias_s[to * 8 + 4];
#pragma unroll
    for (int i = 0; i < 4; i++) {
        float2 c[8];
#pragma unroll
        for (int j = 0; j < 8; j++) c[j] = unpackf2(acc2[i][j]);
        size_t r0 = (size_t)(tb * 8 + 2 * i) * 262144;
        size_t r1 = r0 + 262144;
        *(float4*)(out + r0 + coloff0) =
            make_float4(c[0].x + bv0.x, c[1].x + bv0.y, c[2].x + bv0.z, c[3].x + bv0.w);
        *(float4*)(out + r0 + coloff1) =
            make_float4(c[4].x + bv1.x, c[5].x + bv1.y, c[6].x + bv1.z, c[7].x + bv1.w);
        *(float4*)(out + r1 + coloff0) =
            make_float4(c[0].y + bv0.x, c[1].y + bv0.y, c[2].y + bv0.z, c[3].y + bv0.w);
        *(float4*)(out + r1 + coloff1) =
            make_float4(c[4].y + bv1.x, c[5].y + bv1.y, c[6].y + bv1.z, c[7].y + bv1.w);
    }
}

extern "C" void kernel_launch(void* const* d_in, const int* in_sizes, int n_in,
                              void* d_out, int out_size) {
    const float* x = (const float*)d_in[0];   // (256, 64, 16, 16)
    const float* W = (const float*)d_in[1];   // (256, 1024, 64)
    const float* b = (const float*)d_in[2];   // (256, 1024)
    float* out = (float*)d_out;               // (256, 64, 64, 64)
    (void)in_sizes; (void)n_in; (void)out_size;

    cudaFuncSetAttribute(gemm_kernel, cudaFuncAttributeMaxDynamicSharedMemorySize, SMEM_BYTES);

    transpose32_kernel<<<dim3(8, 8, 64), dim3(32, 8)>>>(x);
    gemm_kernel<<<dim3(16, 256), 256, SMEM_BYTES>>>(W, b, out);
}